// round 17
// baseline (speedup 1.0000x reference)
#include <cuda_runtime.h>
#include <cstdint>

#define N_NODES 50000
#define N_EDGES 200000
#define OUTD 32
#define IN_SELF 128
#define EDGE_DIM 16

#define EDGE_BLOCKS 592
#define EDGE_THREADS 256

#define BN 64            // nodes per block
#define NT 128           // 4 warps x 16 nodes
#define NODE_BLOCKS 782  // ceil(50000/64)
#define XS_PAD 36        // bank(row*36+col) == unique lane for fragment loads

__device__ float g_scratch[N_NODES * OUTD + N_NODES];

__device__ __forceinline__ void red_add_v4(float* ptr, float4 v) {
    asm volatile("red.global.add.v4.f32 [%0], {%1, %2, %3, %4};"
                 :: "l"(ptr), "f"(v.x), "f"(v.y), "f"(v.z), "f"(v.w)
                 : "memory");
}

__device__ __forceinline__ uint32_t f2tf32(float x) {
    uint32_t r;
    asm("cvt.rna.tf32.f32 %0, %1;" : "=r"(r) : "f"(x));
    return r;
}

__device__ __forceinline__ void mma_tf32(float* c, const uint32_t* a,
                                         const uint32_t* b) {
    asm volatile(
        "mma.sync.aligned.m16n8k8.row.col.f32.tf32.tf32.f32 "
        "{%0,%1,%2,%3}, {%4,%5,%6,%7}, {%8,%9}, {%0,%1,%2,%3};"
        : "+f"(c[0]), "+f"(c[1]), "+f"(c[2]), "+f"(c[3])
        : "r"(a[0]), "r"(a[1]), "r"(a[2]), "r"(a[3]), "r"(b[0]), "r"(b[1]));
}

// ---------------------------------------------------------------------------
// Edge kernel (R10 verbatim, proven): software-pipelined scatter.
// ---------------------------------------------------------------------------
__global__ void __launch_bounds__(EDGE_THREADS)
edge_kernel(const float* __restrict__ h_neigh,
            const float* __restrict__ edge_features,
            const float* __restrict__ W_edge,
            const float* __restrict__ b_edge,
            const int* __restrict__ src,
            const int* __restrict__ dst) {
    __shared__ __align__(16) float sW[EDGE_DIM * OUTD];
    __shared__ __align__(16) float sb[OUTD];
    {
        for (int idx = threadIdx.x; idx < OUTD * EDGE_DIM; idx += EDGE_THREADS) {
            int j = idx >> 4, k = idx & 15;
            float s = 0.f;
            #pragma unroll
            for (int i = 0; i < OUTD; i++)
                s += W_edge[(i * OUTD + j) * EDGE_DIM + k];
            sW[k * OUTD + j] = s;
        }
        if (threadIdx.x < OUTD) {
            float s2 = 0.f;
            #pragma unroll
            for (int i = 0; i < OUTD; i++)
                s2 += b_edge[i * OUTD + threadIdx.x];
            sb[threadIdx.x] = s2;
        }
    }
    __syncthreads();

    float* g_agg = g_scratch;
    float* g_deg = g_scratch + N_NODES * OUTD;

    const int lane = threadIdx.x & 31;
    const int warp = threadIdx.x >> 5;
    const int g = lane >> 3;
    const int p = lane & 7;
    const int wpb = EDGE_THREADS >> 5;
    const int nwarps = EDGE_BLOCKS * wpb;
    const int NGROUPS = N_EDGES / 4;

    const float4 biasv = *reinterpret_cast<const float4*>(&sb[4 * p]);

    int grp = blockIdx.x * wpb + warp;
    if (grp >= NGROUPS) return;

    int s = src[grp * 4 + g];
    int d = dst[grp * 4 + g];
    float2 ef = *reinterpret_cast<const float2*>(
        &edge_features[grp * 4 * EDGE_DIM + lane * 2]);

    #pragma unroll 1
    while (true) {
        float4 hv = *reinterpret_cast<const float4*>(&h_neigh[s * OUTD + 4 * p]);

        int next = grp + nwarps;
        int s2 = 0, d2 = 0;
        float2 ef2 = make_float2(0.f, 0.f);
        bool more = (next < NGROUPS);
        if (more) {
            s2 = src[next * 4 + g];
            d2 = dst[next * 4 + g];
            ef2 = *reinterpret_cast<const float2*>(
                &edge_features[next * 4 * EDGE_DIM + lane * 2]);
        }

        float4 acc = biasv;
        #pragma unroll
        for (int k = 0; k < EDGE_DIM; k++) {
            float ek = __shfl_sync(0xffffffffu, (k & 1) ? ef.y : ef.x, k >> 1, 8);
            float4 w = *reinterpret_cast<const float4*>(&sW[k * OUTD + 4 * p]);
            acc.x = fmaf(ek, w.x, acc.x);
            acc.y = fmaf(ek, w.y, acc.y);
            acc.z = fmaf(ek, w.z, acc.z);
            acc.w = fmaf(ek, w.w, acc.w);
        }

        float4 msg = make_float4(hv.x * acc.x, hv.y * acc.y,
                                 hv.z * acc.z, hv.w * acc.w);
        red_add_v4(&g_agg[d * OUTD + 4 * p], msg);
        if (p == 0) atomicAdd(&g_deg[d], 1.0f);

        if (!more) break;
        s = s2; d = d2; ef = ef2; grp = next;
    }
}

// ---------------------------------------------------------------------------
// Node kernel: 3xTF32 warp-MMA GEMM, 16 nodes/warp, double-buffered +
// register-prefetched staging.  Fragment mappings identical to R16 (verified).
// ---------------------------------------------------------------------------
__global__ void __launch_bounds__(NT, 4)
node_kernel(const float* __restrict__ h_self,
            const float* __restrict__ W_self,
            const float* __restrict__ W_neigh,
            float* __restrict__ out) {
    __shared__ float xs[2][BN][XS_PAD];    // 18KB
    __shared__ float wh[2][OUTD][XS_PAD];  // 9KB
    __shared__ float wl[2][OUTD][XS_PAD];  // 9KB
    __shared__ float sinv[BN];

    float* g_agg = g_scratch;
    float* g_deg = g_scratch + N_NODES * OUTD;

    const int t = threadIdx.x;
    const int w = t >> 5;
    const int lane = t & 31;
    const int g = lane >> 2;       // groupID 0..7
    const int tig = lane & 3;      // thread-in-group
    const int nbase = blockIdx.x * BN;

    // sinv + deg self-clean
    if (t < BN) {
        int gn = nbase + t;
        if (gn < N_NODES) {
            float dv = g_deg[gn];
            g_deg[gn] = 0.f;
            sinv[t] = 1.0f / fmaxf(dv, 1.0f);
        } else {
            sinv[t] = 0.f;
        }
    }

    // prefetch registers
    float4 xreg[4];
    float wreg[8];

    auto load_regs = [&](int kc) {
        #pragma unroll
        for (int i = 0; i < 4; i++) {
            int idx = t + i * NT;          // 0..511
            int node = idx >> 3;           // 0..63
            int kvec = idx & 7;
            int gn = nbase + node;
            float4 v = make_float4(0.f, 0.f, 0.f, 0.f);
            if (gn < N_NODES) {
                if (kc < 4) {
                    v = *reinterpret_cast<const float4*>(
                        &h_self[gn * IN_SELF + kc * 32 + kvec * 4]);
                } else {
                    v = *reinterpret_cast<const float4*>(
                        &g_agg[gn * OUTD + kvec * 4]);
                    float iv = sinv[node];
                    v.x *= iv; v.y *= iv; v.z *= iv; v.w *= iv;
                }
            }
            xreg[i] = v;
        }
        #pragma unroll
        for (int i = 0; i < 8; i++) {
            int idx = t + i * NT;          // 0..1023
            int c = idx >> 5;              // 0..31
            int k = idx & 31;
            wreg[i] = (kc < 4) ? W_self[c * IN_SELF + kc * 32 + k]
                               : W_neigh[c * OUTD + k];
        }
    };

    auto store_smem = [&](int b) {
        #pragma unroll
        for (int i = 0; i < 4; i++) {
            int idx = t + i * NT;
            int node = idx >> 3;
            int kvec = idx & 7;
            *reinterpret_cast<float4*>(&xs[b][node][kvec * 4]) = xreg[i];
        }
        #pragma unroll
        for (int i = 0; i < 8; i++) {
            int idx = t + i * NT;
            int c = idx >> 5;
            int k = idx & 31;
            uint32_t hb = f2tf32(wreg[i]);
            float hf = __uint_as_float(hb);
            wh[b][c][k] = hf;
            wl[b][c][k] = wreg[i] - hf;
        }
    };

    // accumulators: 1 m16 frag x 4 n8 frags
    float acc[4][4];
    #pragma unroll
    for (int nf = 0; nf < 4; nf++)
        #pragma unroll
        for (int q = 0; q < 4; q++) acc[nf][q] = 0.f;

    load_regs(0);
    __syncthreads();      // sinv visible
    store_smem(0);
    __syncthreads();

    #pragma unroll
    for (int kc = 0; kc < 5; kc++) {
        int b = kc & 1;
        if (kc < 4) load_regs(kc + 1);     // prefetch overlaps compute below
        #pragma unroll
        for (int ks = 0; ks < 4; ks++) {
            int kb = ks * 8;
            // A fragment (hi + lo), rows = w*16 + {g, g+8}, cols kb+{tig,tig+4}
            uint32_t ahi[4], alo[4];
            #pragma unroll
            for (int j = 0; j < 4; j++) {
                int row = w * 16 + g + (j & 1) * 8;
                int col = kb + tig + (j >> 1) * 4;
                float x = xs[b][row][col];
                uint32_t hb = f2tf32(x);
                ahi[j] = hb;
                alo[j] = __float_as_uint(x - __uint_as_float(hb));
            }
            // B fragments (hi + lo), 4 n8 tiles
            uint32_t bhi[4][2], blo[4][2];
            #pragma unroll
            for (int nf = 0; nf < 4; nf++) {
                int ch = nf * 8 + g;
                bhi[nf][0] = __float_as_uint(wh[b][ch][kb + tig]);
                bhi[nf][1] = __float_as_uint(wh[b][ch][kb + tig + 4]);
                blo[nf][0] = __float_as_uint(wl[b][ch][kb + tig]);
                blo[nf][1] = __float_as_uint(wl[b][ch][kb + tig + 4]);
            }
            #pragma unroll
            for (int nf = 0; nf < 4; nf++) {
                mma_tf32(acc[nf], ahi, bhi[nf]);
                mma_tf32(acc[nf], ahi, blo[nf]);
                mma_tf32(acc[nf], alo, bhi[nf]);
            }
        }
        if (kc < 4) store_smem(1 - b);
        __syncthreads();
    }

    // ---- epilogue: relu + float2 stores ----
    #pragma unroll
    for (int nf = 0; nf < 4; nf++) {
        int col = nf * 8 + 2 * tig;
        int n0 = nbase + w * 16 + g;
        int n1 = n0 + 8;
        if (n0 < N_NODES) {
            float2 o0 = make_float2(fmaxf(acc[nf][0], 0.f),
                                    fmaxf(acc[nf][1], 0.f));
            *reinterpret_cast<float2*>(&out[n0 * OUTD + col]) = o0;
        }
        if (n1 < N_NODES) {
            float2 o1 = make_float2(fmaxf(acc[nf][2], 0.f),
                                    fmaxf(acc[nf][3], 0.f));
            *reinterpret_cast<float2*>(&out[n1 * OUTD + col]) = o1;
        }
    }

    // ---- bulk self-clean of this block's agg slice ----
    {
        const int nvalid = min(BN, N_NODES - nbase);
        const int nq = nvalid * (OUTD / 4);
        float4* ap = reinterpret_cast<float4*>(&g_agg[nbase * OUTD]);
        const float4 z = make_float4(0.f, 0.f, 0.f, 0.f);
        for (int i = t; i < nq; i += NT)
            ap[i] = z;
    }
}

extern "C" void kernel_launch(void* const* d_in, const int* in_sizes, int n_in,
                              void* d_out, int out_size) {
    const float* h_neigh       = (const float*)d_in[0];
    const float* h_self        = (const float*)d_in[1];
    const float* edge_features = (const float*)d_in[2];
    const float* W_edge        = (const float*)d_in[3];
    const float* b_edge        = (const float*)d_in[4];
    const float* W_self        = (const float*)d_in[5];
    const float* W_neigh       = (const float*)d_in[6];
    const int*   src           = (const int*)d_in[7];
    const int*   dst           = (const int*)d_in[8];
    float* out = (float*)d_out;

    // Two launches, no memset: scratch zeroed at load; node_kernel restores
    // zeros (deg in sinv setup, agg post-epilogue) -> replay-safe.
    edge_kernel<<<EDGE_BLOCKS, EDGE_THREADS>>>(h_neigh, edge_features,
                                               W_edge, b_edge, src, dst);
    node_kernel<<<NODE_BLOCKS, NT>>>(h_self, W_self, W_neigh, out);
}